// round 9
// baseline (speedup 1.0000x reference)
#include <cuda_runtime.h>
#include <cuda_bf16.h>
#include <cstdint>
#include <math.h>

#define DEV __device__ __forceinline__

static constexpr int Mdim = 8192, Kdim = 4096, Ndim = 4096;
static constexpr int BM = 128, BN = 128, BK = 64;       // BK=64 fp8 elements = 64B rows
static constexpr int STAGES = 4;
static constexpr int NK  = Kdim / BK;                   // 64 K-iters
static constexpr int NTM = Mdim / BM;                   // 64
static constexpr int NTN = Ndim / BN;                   // 32
static constexpr int A_SZ = BM * 64;                    // 8 KB  (128 rows x 64B)
static constexpr int B_SZ = BN * 64;                    // 8 KB
static constexpr int STAGE_BYTES = A_SZ + B_SZ;         // 16 KB
static constexpr int SMEM_BIAS  = 0;                    // 128 floats
static constexpr int SMEM_TILES = 1024;
static constexpr int SMEM_TOTAL = SMEM_TILES + STAGES * STAGE_BYTES;  // 66560
static constexpr int NPART = NTN * 4;                   // 128 partials per row
static constexpr float WSCALE_INV = 1.0f / 64.0f;       // W stored as W*64 in fp8

// Scratch (__device__ globals: the sanctioned no-alloc path)
__device__ __align__(16) unsigned char g_Xf8[(size_t)Mdim * Kdim];
__device__ __align__(16) unsigned char g_Wf8[(size_t)Ndim * Kdim];
__device__ float g_partial[(size_t)Mdim * NPART];

// ---------------------------------------------------------------- helpers
DEV uint32_t smem_u32(const void* p) {
    uint32_t a;
    asm("{ .reg .u64 t; cvta.to.shared.u64 t, %1; cvt.u32.u64 %0, t; }"
        : "=r"(a) : "l"(p));
    return a;
}
// SW64-style swizzle for 64B-wide rows: 16B-chunk c' = c ^ ((row>>1)&3).
// Conflict-free for cp.async stores and all ldmatrix 8-address groups.
DEV uint32_t swz64(uint32_t off) { return off ^ ((off >> 3) & 0x30); }

DEV void cpa16(uint32_t d, const void* s) {
    asm volatile("cp.async.cg.shared.global [%0], [%1], 16;" :: "r"(d), "l"(s));
}
DEV void cp_commit() { asm volatile("cp.async.commit_group;" ::: "memory"); }
DEV void cp_wait2()  { asm volatile("cp.async.wait_group 2;" ::: "memory"); }

DEV void ldsm_x4(uint32_t (&r)[4], uint32_t addr) {
    asm volatile("ldmatrix.sync.aligned.m8n8.x4.shared.b16 {%0,%1,%2,%3}, [%4];"
                 : "=r"(r[0]), "=r"(r[1]), "=r"(r[2]), "=r"(r[3]) : "r"(addr));
}
// FP8 e4m3 MMA, K=32, f32 accumulate (sm_89+ base PTX)
DEV void mma16832(float (&d)[4], const uint32_t (&a)[4], uint32_t b0, uint32_t b1) {
    asm volatile(
        "mma.sync.aligned.m16n8k32.row.col.f32.e4m3.e4m3.f32 "
        "{%0,%1,%2,%3}, {%4,%5,%6,%7}, {%8,%9}, {%0,%1,%2,%3};"
        : "+f"(d[0]), "+f"(d[1]), "+f"(d[2]), "+f"(d[3])
        : "r"(a[0]), "r"(a[1]), "r"(a[2]), "r"(a[3]), "r"(b0), "r"(b1));
}

// pack 2 floats -> e4m3x2 (first asm operand lands in HIGH byte)
DEV uint16_t cvt2_e4m3(float lo, float hi) {
    uint16_t r;
    asm("cvt.rn.satfinite.e4m3x2.f32 %0, %1, %2;" : "=h"(r) : "f"(hi), "f"(lo));
    return r;
}

// activation chain + exp (matches reference exactly, in fp32)
DEV float act_exp(float v) {
    v = (v > 0.0f) ? v : 1e-4f * v;            // leaky(0.01) twice
#pragma unroll
    for (int g = 0; g < 2; g++) {              // softsign-GELU twice
        float t = 0.7978845608f * fmaf(0.044715f * v * v, v, v);
        v = 0.5f * v * (1.0f + __fdividef(t, 1.0f + fabsf(t)));
    }
    return __expf(v);
}

// ------------------------------------------------------------- fp32 -> e4m3
__global__ void cvt_x_kernel(const float4* __restrict__ src, int n16) {
    int i = blockIdx.x * blockDim.x + threadIdx.x;
    if (i >= n16) return;
    uint32_t w[4];
#pragma unroll
    for (int q = 0; q < 4; q++) {
        float4 f = src[4 * i + q];
        w[q] = (uint32_t)cvt2_e4m3(f.x, f.y) |
               ((uint32_t)cvt2_e4m3(f.z, f.w) << 16);
    }
    reinterpret_cast<uint4*>(g_Xf8)[i] = make_uint4(w[0], w[1], w[2], w[3]);
}
__global__ void cvt_w_kernel(const float4* __restrict__ src, int n16) {
    int i = blockIdx.x * blockDim.x + threadIdx.x;
    if (i >= n16) return;
    uint32_t w[4];
#pragma unroll
    for (int q = 0; q < 4; q++) {
        float4 f = src[4 * i + q];
        w[q] = (uint32_t)cvt2_e4m3(f.x * 64.0f, f.y * 64.0f) |
               ((uint32_t)cvt2_e4m3(f.z * 64.0f, f.w * 64.0f) << 16);
    }
    reinterpret_cast<uint4*>(g_Wf8)[i] = make_uint4(w[0], w[1], w[2], w[3]);
}

// ------------------------------------------------------------- GEMM + epilogue
__global__ void __launch_bounds__(256, 2) gemm_lse_kernel(const float* __restrict__ bias) {
    extern __shared__ char smem[];
    const uint32_t sb = smem_u32(smem);
    const int tid   = threadIdx.x;
    const int lane  = tid & 31;
    const int wid   = tid >> 5;
    const int mwarp = wid >> 2;              // 0..1  (64-row slice)
    const int nwarp = wid & 3;               // 0..3  (32-col slice)
    const int m0 = blockIdx.x * BM;
    const int n0 = blockIdx.y * BN;

    if (tid < BN) reinterpret_cast<float*>(smem + SMEM_BIAS)[tid] = bias[n0 + tid];

    // ---- cp.async slots: 512 x 16B chunks per operand, 2 per thread ----
    uint32_t aDst[2], bDst[2];
    const unsigned char *aSrc[2], *bSrc[2];
#pragma unroll
    for (int t = 0; t < 2; t++) {
        int cid = tid + t * 256;
        int r = cid >> 2, c = cid & 3;                  // row, 16B-chunk
        uint32_t off = swz64((uint32_t)(r * 64 + c * 16));
        aDst[t] = sb + SMEM_TILES + off;
        bDst[t] = sb + SMEM_TILES + A_SZ + off;
        aSrc[t] = g_Xf8 + (size_t)(m0 + r) * Kdim + c * 16;
        bSrc[t] = g_Wf8 + (size_t)(n0 + r) * Kdim + c * 16;
    }

    // ---- ldmatrix per-lane offsets (within stage), NON-trans ----
    // fp8 k32 fragments: ldmatrix m8n8 gives lane i -> mat-row i/4, bytes 4(i%4):
    // exactly the e4m3 m16n8k32 A/B fragment layout (16B mat-row = 16 fp8 = kc).
    // A x4 mats: (m0-7,kc0),(m8-15,kc0),(m0-7,kc1),(m8-15,kc1); mt*1024 = +16 rows
    // B x4 mats: (n-oct0,kc0),(n-oct0,kc1),(n-oct1,kc0),(n-oct1,kc1); np*1024 = +16
    uint32_t aOff[2], bOff[2];
#pragma unroll
    for (int kk = 0; kk < 2; kk++) {        // kk = k32 half of the K=64 chunk
        uint32_t ar = (uint32_t)(mwarp * 64 + (lane & 15));
        aOff[kk] = SMEM_TILES +
                   swz64(ar * 64 + (uint32_t)(kk * 32 + (lane >> 4) * 16));
        uint32_t br = (uint32_t)(nwarp * 32 + ((lane >> 4) & 1) * 8 + (lane & 7));
        bOff[kk] = SMEM_TILES + A_SZ +
                   swz64(br * 64 + (uint32_t)(kk * 32 + ((lane >> 3) & 1) * 16));
    }

    float acc[4][4][4];
#pragma unroll
    for (int mt = 0; mt < 4; mt++)
#pragma unroll
        for (int nt = 0; nt < 4; nt++)
#pragma unroll
            for (int j = 0; j < 4; j++) acc[mt][nt][j] = 0.0f;

    // ---- prologue: stages 0..2 ----
#pragma unroll
    for (int s = 0; s < STAGES - 1; s++) {
        uint32_t sB = (uint32_t)(s * STAGE_BYTES);
        int k0 = s * BK;
#pragma unroll
        for (int t = 0; t < 2; t++) {
            cpa16(aDst[t] + sB, aSrc[t] + k0);
            cpa16(bDst[t] + sB, bSrc[t] + k0);
        }
        cp_commit();
    }

    // ---- mainloop: 64 iters, each consumes K=64 (2 x k32 MMA steps) ----
    for (int i = 0; i < NK; i++) {
        cp_wait2();
        __syncthreads();
        uint32_t sB = (uint32_t)((i & (STAGES - 1)) * STAGE_BYTES);
#pragma unroll
        for (int kk = 0; kk < 2; kk++) {
            uint32_t a[4][4];
#pragma unroll
            for (int mt = 0; mt < 4; mt++)
                ldsm_x4(a[mt], sb + sB + aOff[kk] + mt * 1024);
            uint32_t b[2][4];            // b[np]: r0,r1 = n-oct(2np) kc0,kc1; r2,r3 = n-oct(2np+1)
#pragma unroll
            for (int np = 0; np < 2; np++)
                ldsm_x4(b[np], sb + sB + bOff[kk] + np * 1024);
#pragma unroll
            for (int mt = 0; mt < 4; mt++)
#pragma unroll
                for (int nt = 0; nt < 4; nt++)
                    mma16832(acc[mt][nt], a[mt],
                             b[nt >> 1][(nt & 1) * 2], b[nt >> 1][(nt & 1) * 2 + 1]);
        }
        int j = i + STAGES - 1;
        if (j < NK) {
            uint32_t fB = (uint32_t)((j & (STAGES - 1)) * STAGE_BYTES);
            int k0 = j * BK;
#pragma unroll
            for (int t = 0; t < 2; t++) {
                cpa16(aDst[t] + fB, aSrc[t] + k0);
                cpa16(bDst[t] + fB, bSrc[t] + k0);
            }
        }
        cp_commit();
    }

    // ---- epilogue: unscale + bias + activations + exp + row partial sums ----
    const float* bs = reinterpret_cast<const float*>(smem + SMEM_BIAS);
    const int part = blockIdx.y * 4 + nwarp;
#pragma unroll
    for (int mt = 0; mt < 4; mt++) {
        float sA = 0.0f, sB2 = 0.0f;
#pragma unroll
        for (int nt = 0; nt < 4; nt++) {
            int col = nwarp * 32 + nt * 8 + (lane & 3) * 2;
            float b0 = bs[col], b1 = bs[col + 1];
            sA  += act_exp(fmaf(acc[mt][nt][0], WSCALE_INV, b0)) +
                   act_exp(fmaf(acc[mt][nt][1], WSCALE_INV, b1));
            sB2 += act_exp(fmaf(acc[mt][nt][2], WSCALE_INV, b0)) +
                   act_exp(fmaf(acc[mt][nt][3], WSCALE_INV, b1));
        }
        // combine the 4 lanes (lane&3) that share these two rows
        sA  += __shfl_xor_sync(0xFFFFFFFFu, sA, 1);
        sA  += __shfl_xor_sync(0xFFFFFFFFu, sA, 2);
        sB2 += __shfl_xor_sync(0xFFFFFFFFu, sB2, 1);
        sB2 += __shfl_xor_sync(0xFFFFFFFFu, sB2, 2);
        if ((lane & 3) == 0) {
            int row = m0 + mwarp * 64 + mt * 16 + (lane >> 2);
            g_partial[(size_t)row * NPART + part]       = sA;
            g_partial[(size_t)(row + 8) * NPART + part] = sB2;
        }
    }
}

// ------------------------------------------------------------- final reduce
// Warp per row: coalesced reads, shfl tree (fixed order -> deterministic).
__global__ void lse_kernel(float* __restrict__ out) {
    int warp = (int)((blockIdx.x * blockDim.x + threadIdx.x) >> 5);
    int lane = threadIdx.x & 31;
    if (warp >= Mdim) return;
    const float* p = g_partial + (size_t)warp * NPART;
    float s = (p[lane] + p[lane + 32]) + (p[lane + 64] + p[lane + 96]);
#pragma unroll
    for (int o = 16; o; o >>= 1) s += __shfl_xor_sync(0xFFFFFFFFu, s, o);
    if (lane == 0) out[warp] = logf(s);
}

// ------------------------------------------------------------- launch
extern "C" void kernel_launch(void* const* d_in, const int* in_sizes, int n_in,
                              void* d_out, int out_size) {
    const float* x = (const float*)d_in[0];
    const float* W = (const float*)d_in[1];
    const float* b = (const float*)d_in[2];
    float* out = (float*)d_out;

    cudaFuncSetAttribute(gemm_lse_kernel,
                         cudaFuncAttributeMaxDynamicSharedMemorySize, SMEM_TOTAL);

    int n16x = Mdim * Kdim / 16;
    cvt_x_kernel<<<(n16x + 255) / 256, 256>>>((const float4*)x, n16x);
    int n16w = Ndim * Kdim / 16;
    cvt_w_kernel<<<(n16w + 255) / 256, 256>>>((const float4*)W, n16w);

    gemm_lse_kernel<<<dim3(NTM, NTN), 256, SMEM_TOTAL>>>(b);
    lse_kernel<<<(Mdim * 32 + 255) / 256, 256>>>(out);
}

// round 11
// speedup vs baseline: 1.0020x; 1.0020x over previous
#include <cuda_runtime.h>
#include <cuda_bf16.h>
#include <cstdint>
#include <math.h>

#define DEV __device__ __forceinline__

static constexpr int Mdim = 8192, Kdim = 4096, Ndim = 4096;
static constexpr int BM = 128, BN = 128, BK = 64;       // BK=64 fp8 elements = 64B rows
static constexpr int STAGES = 6;
static constexpr int NK  = Kdim / BK;                   // 64 K-iters
static constexpr int NTM = Mdim / BM;                   // 64
static constexpr int NTN = Ndim / BN;                   // 32
static constexpr int A_SZ = BM * 64;                    // 8 KB  (128 rows x 64B)
static constexpr int B_SZ = BN * 64;                    // 8 KB
static constexpr int STAGE_BYTES = A_SZ + B_SZ;         // 16 KB
static constexpr int SMEM_BIAS  = 0;                    // 128 floats
static constexpr int SMEM_TILES = 1024;
static constexpr int SMEM_TOTAL = SMEM_TILES + STAGES * STAGE_BYTES;  // 99328
static constexpr int NPART = NTN * 4;                   // 128 partials per row
static constexpr float WSCALE_INV = 1.0f / 64.0f;       // W stored as W*64 in fp8

// Scratch (__device__ globals: the sanctioned no-alloc path)
__device__ __align__(16) unsigned char g_Xf8[(size_t)Mdim * Kdim];
__device__ __align__(16) unsigned char g_Wf8[(size_t)Ndim * Kdim];
__device__ float g_partial[(size_t)Mdim * NPART];

// ---------------------------------------------------------------- helpers
DEV uint32_t smem_u32(const void* p) {
    uint32_t a;
    asm("{ .reg .u64 t; cvta.to.shared.u64 t, %1; cvt.u32.u64 %0, t; }"
        : "=r"(a) : "l"(p));
    return a;
}
// SW64-style swizzle for 64B-wide rows: 16B-chunk c' = c ^ ((row>>1)&3).
// Conflict-free for cp.async stores and all ldmatrix 8-address groups.
DEV uint32_t swz64(uint32_t off) { return off ^ ((off >> 3) & 0x30); }

DEV void cpa16(uint32_t d, const void* s) {
    asm volatile("cp.async.cg.shared.global [%0], [%1], 16;" :: "r"(d), "l"(s));
}
DEV void cp_commit() { asm volatile("cp.async.commit_group;" ::: "memory"); }
DEV void cp_wait4()  { asm volatile("cp.async.wait_group 4;" ::: "memory"); }

DEV void ldsm_x4(uint32_t (&r)[4], uint32_t addr) {
    asm volatile("ldmatrix.sync.aligned.m8n8.x4.shared.b16 {%0,%1,%2,%3}, [%4];"
                 : "=r"(r[0]), "=r"(r[1]), "=r"(r[2]), "=r"(r[3]) : "r"(addr));
}
// FP8 e4m3 MMA, K=32, f32 accumulate (sm_89+ base PTX)
DEV void mma16832(float (&d)[4], const uint32_t (&a)[4], uint32_t b0, uint32_t b1) {
    asm volatile(
        "mma.sync.aligned.m16n8k32.row.col.f32.e4m3.e4m3.f32 "
        "{%0,%1,%2,%3}, {%4,%5,%6,%7}, {%8,%9}, {%0,%1,%2,%3};"
        : "+f"(d[0]), "+f"(d[1]), "+f"(d[2]), "+f"(d[3])
        : "r"(a[0]), "r"(a[1]), "r"(a[2]), "r"(a[3]), "r"(b0), "r"(b1));
}

// pack 2 floats -> e4m3x2 (first asm operand lands in HIGH byte)
DEV uint16_t cvt2_e4m3(float lo, float hi) {
    uint16_t r;
    asm("cvt.rn.satfinite.e4m3x2.f32 %0, %1, %2;" : "=h"(r) : "f"(hi), "f"(lo));
    return r;
}

// activation chain + exp (matches reference exactly, in fp32)
DEV float act_exp(float v) {
    v = (v > 0.0f) ? v : 1e-4f * v;            // leaky(0.01) twice
#pragma unroll
    for (int g = 0; g < 2; g++) {              // softsign-GELU twice
        float t = 0.7978845608f * fmaf(0.044715f * v * v, v, v);
        v = 0.5f * v * (1.0f + __fdividef(t, 1.0f + fabsf(t)));
    }
    return __expf(v);
}

// ------------------------------------------------------------- fp32 -> e4m3
// One fused kernel: X (no scale) then W (x64 scale).
__global__ void cvt_kernel(const float4* __restrict__ x, const float4* __restrict__ w,
                           int n16x, int n16w) {
    int i = blockIdx.x * blockDim.x + threadIdx.x;
    if (i < n16x) {
        uint32_t o[4];
#pragma unroll
        for (int q = 0; q < 4; q++) {
            float4 f = x[4 * i + q];
            o[q] = (uint32_t)cvt2_e4m3(f.x, f.y) |
                   ((uint32_t)cvt2_e4m3(f.z, f.w) << 16);
        }
        reinterpret_cast<uint4*>(g_Xf8)[i] = make_uint4(o[0], o[1], o[2], o[3]);
    } else if (i - n16x < n16w) {
        int j = i - n16x;
        uint32_t o[4];
#pragma unroll
        for (int q = 0; q < 4; q++) {
            float4 f = w[4 * j + q];
            o[q] = (uint32_t)cvt2_e4m3(f.x * 64.0f, f.y * 64.0f) |
                   ((uint32_t)cvt2_e4m3(f.z * 64.0f, f.w * 64.0f) << 16);
        }
        reinterpret_cast<uint4*>(g_Wf8)[j] = make_uint4(o[0], o[1], o[2], o[3]);
    }
}

// ------------------------------------------------------------- GEMM + epilogue
__global__ void __launch_bounds__(256, 2) gemm_lse_kernel(const float* __restrict__ bias) {
    extern __shared__ char smem[];
    const uint32_t sb = smem_u32(smem);
    const int tid   = threadIdx.x;
    const int lane  = tid & 31;
    const int wid   = tid >> 5;
    const int mwarp = wid >> 2;              // 0..1  (64-row slice)
    const int nwarp = wid & 3;               // 0..3  (32-col slice)
    const int m0 = blockIdx.x * BM;
    const int n0 = blockIdx.y * BN;

    if (tid < BN) reinterpret_cast<float*>(smem + SMEM_BIAS)[tid] = bias[n0 + tid];

    // ---- cp.async slots: 512 x 16B chunks per operand, 2 per thread ----
    uint32_t aDst[2], bDst[2];
    const unsigned char *aSrc[2], *bSrc[2];
#pragma unroll
    for (int t = 0; t < 2; t++) {
        int cid = tid + t * 256;
        int r = cid >> 2, c = cid & 3;                  // row, 16B-chunk
        uint32_t off = swz64((uint32_t)(r * 64 + c * 16));
        aDst[t] = sb + SMEM_TILES + off;
        bDst[t] = sb + SMEM_TILES + A_SZ + off;
        aSrc[t] = g_Xf8 + (size_t)(m0 + r) * Kdim + c * 16;
        bSrc[t] = g_Wf8 + (size_t)(n0 + r) * Kdim + c * 16;
    }

    // ---- ldmatrix per-lane offsets (within stage), NON-trans ----
    // fp8 k32 fragments: ldmatrix m8n8 gives lane i -> mat-row i/4, bytes 4(i%4):
    // exactly the e4m3 m16n8k32 A/B fragment layout (16B mat-row = 16 fp8 = kc).
    uint32_t aOff[2], bOff[2];
#pragma unroll
    for (int kk = 0; kk < 2; kk++) {        // kk = k32 half of the K=64 chunk
        uint32_t ar = (uint32_t)(mwarp * 64 + (lane & 15));
        aOff[kk] = SMEM_TILES +
                   swz64(ar * 64 + (uint32_t)(kk * 32 + (lane >> 4) * 16));
        uint32_t br = (uint32_t)(nwarp * 32 + ((lane >> 4) & 1) * 8 + (lane & 7));
        bOff[kk] = SMEM_TILES + A_SZ +
                   swz64(br * 64 + (uint32_t)(kk * 32 + ((lane >> 3) & 1) * 16));
    }

    float acc[4][4][4];
#pragma unroll
    for (int mt = 0; mt < 4; mt++)
#pragma unroll
        for (int nt = 0; nt < 4; nt++)
#pragma unroll
            for (int j = 0; j < 4; j++) acc[mt][nt][j] = 0.0f;

    // ---- prologue: stages 0..4 (chunks 0..4) ----
#pragma unroll
    for (int s = 0; s < STAGES - 1; s++) {
        uint32_t sB = (uint32_t)(s * STAGE_BYTES);
        int k0 = s * BK;
#pragma unroll
        for (int t = 0; t < 2; t++) {
            cpa16(aDst[t] + sB, aSrc[t] + k0);
            cpa16(bDst[t] + sB, bSrc[t] + k0);
        }
        cp_commit();
    }

    // ---- mainloop: refill-first, then consume (loads fly during the MMAs) ----
    for (int i = 0; i < NK; i++) {
        cp_wait4();          // chunks 0..i resident (<=4 newer groups pending)
        __syncthreads();     // all warps done reading stage (i-1)%S

        int j = i + STAGES - 1;
        if (j < NK) {        // refill stage (i+5)%6 == (i-1)%6 with chunk j
            uint32_t fB = (uint32_t)((j % STAGES) * STAGE_BYTES);
            int k0 = j * BK;
#pragma unroll
            for (int t = 0; t < 2; t++) {
                cpa16(aDst[t] + fB, aSrc[t] + k0);
                cpa16(bDst[t] + fB, bSrc[t] + k0);
            }
        }
        cp_commit();         // always commit (empty group keeps the count)

        uint32_t sB = (uint32_t)((i % STAGES) * STAGE_BYTES);
#pragma unroll
        for (int kk = 0; kk < 2; kk++) {
            uint32_t a[4][4];
#pragma unroll
            for (int mt = 0; mt < 4; mt++)
                ldsm_x4(a[mt], sb + sB + aOff[kk] + mt * 1024);
            uint32_t b[2][4];            // b[np]: r0,r1 = n-oct(2np) kc0,kc1; r2,r3 = n-oct(2np+1)
#pragma unroll
            for (int np = 0; np < 2; np++)
                ldsm_x4(b[np], sb + sB + bOff[kk] + np * 1024);
#pragma unroll
            for (int mt = 0; mt < 4; mt++)
#pragma unroll
                for (int nt = 0; nt < 4; nt++)
                    mma16832(acc[mt][nt], a[mt],
                             b[nt >> 1][(nt & 1) * 2], b[nt >> 1][(nt & 1) * 2 + 1]);
        }
    }

    // ---- epilogue: unscale + bias + activations + exp + row partial sums ----
    const float* bs = reinterpret_cast<const float*>(smem + SMEM_BIAS);
    const int part = blockIdx.y * 4 + nwarp;
#pragma unroll
    for (int mt = 0; mt < 4; mt++) {
        float sA = 0.0f, sB2 = 0.0f;
#pragma unroll
        for (int nt = 0; nt < 4; nt++) {
            int col = nwarp * 32 + nt * 8 + (lane & 3) * 2;
            float b0 = bs[col], b1 = bs[col + 1];
            sA  += act_exp(fmaf(acc[mt][nt][0], WSCALE_INV, b0)) +
                   act_exp(fmaf(acc[mt][nt][1], WSCALE_INV, b1));
            sB2 += act_exp(fmaf(acc[mt][nt][2], WSCALE_INV, b0)) +
                   act_exp(fmaf(acc[mt][nt][3], WSCALE_INV, b1));
        }
        // combine the 4 lanes (lane&3) that share these two rows
        sA  += __shfl_xor_sync(0xFFFFFFFFu, sA, 1);
        sA  += __shfl_xor_sync(0xFFFFFFFFu, sA, 2);
        sB2 += __shfl_xor_sync(0xFFFFFFFFu, sB2, 1);
        sB2 += __shfl_xor_sync(0xFFFFFFFFu, sB2, 2);
        if ((lane & 3) == 0) {
            int row = m0 + mwarp * 64 + mt * 16 + (lane >> 2);
            g_partial[(size_t)row * NPART + part]       = sA;
            g_partial[(size_t)(row + 8) * NPART + part] = sB2;
        }
    }
}

// ------------------------------------------------------------- final reduce
// Warp per row: coalesced reads, shfl tree (fixed order -> deterministic).
__global__ void lse_kernel(float* __restrict__ out) {
    int warp = (int)((blockIdx.x * blockDim.x + threadIdx.x) >> 5);
    int lane = threadIdx.x & 31;
    if (warp >= Mdim) return;
    const float* p = g_partial + (size_t)warp * NPART;
    float s = (p[lane] + p[lane + 32]) + (p[lane + 64] + p[lane + 96]);
#pragma unroll
    for (int o = 16; o; o >>= 1) s += __shfl_xor_sync(0xFFFFFFFFu, s, o);
    if (lane == 0) out[warp] = logf(s);
}

// ------------------------------------------------------------- launch
extern "C" void kernel_launch(void* const* d_in, const int* in_sizes, int n_in,
                              void* d_out, int out_size) {
    const float* x = (const float*)d_in[0];
    const float* W = (const float*)d_in[1];
    const float* b = (const float*)d_in[2];
    float* out = (float*)d_out;

    cudaFuncSetAttribute(gemm_lse_kernel,
                         cudaFuncAttributeMaxDynamicSharedMemorySize, SMEM_TOTAL);

    int n16x = Mdim * Kdim / 16;
    int n16w = Ndim * Kdim / 16;
    cvt_kernel<<<(n16x + n16w + 255) / 256, 256>>>((const float4*)x, (const float4*)W,
                                                   n16x, n16w);

    gemm_lse_kernel<<<dim3(NTM, NTN), 256, SMEM_TOTAL>>>(b);
    lse_kernel<<<(Mdim * 32 + 255) / 256, 256>>>(out);
}

// round 12
// speedup vs baseline: 1.1210x; 1.1188x over previous
#include <cuda_runtime.h>
#include <cuda_bf16.h>
#include <cstdint>
#include <math.h>

#define DEV __device__ __forceinline__

static constexpr int Mdim = 8192, Kdim = 4096, Ndim = 4096;
static constexpr int BM = 128, BN = 128, BK = 32;       // CTA tile (R5: measured best)
static constexpr int STAGES = 4;
static constexpr int NK  = Kdim / BK;                   // 128 K-iters
static constexpr int NTM = Mdim / BM;                   // 64
static constexpr int NTN = Ndim / BN;                   // 32
static constexpr int A_SZ = BM * 64;                    // 8 KB  (128 rows x 64B)
static constexpr int B_SZ = BN * 64;                    // 8 KB
static constexpr int STAGE_BYTES = A_SZ + B_SZ;         // 16 KB
static constexpr int SMEM_BIAS  = 0;                    // 128 floats
static constexpr int SMEM_TILES = 1024;
static constexpr int SMEM_TOTAL = SMEM_TILES + STAGES * STAGE_BYTES;  // 66560
static constexpr int NPART = NTN * 4;                   // 128 partials per row

// Scratch (__device__ globals: the sanctioned no-alloc path)
__device__ __align__(16) __nv_bfloat16 g_Xbf[(size_t)Mdim * Kdim];
__device__ __align__(16) __nv_bfloat16 g_Wbf[(size_t)Ndim * Kdim];
__device__ float g_partial[(size_t)Mdim * NPART];

// ---------------------------------------------------------------- helpers
DEV uint32_t smem_u32(const void* p) {
    uint32_t a;
    asm("{ .reg .u64 t; cvta.to.shared.u64 t, %1; cvt.u32.u64 %0, t; }"
        : "=r"(a) : "l"(p));
    return a;
}
// SW64-style swizzle for 64B-wide rows: 16B-chunk c' = c ^ ((row>>1)&3).
// Conflict-free for cp.async stores and all ldmatrix 8-address groups.
DEV uint32_t swz64(uint32_t off) { return off ^ ((off >> 3) & 0x30); }

DEV void cpa16(uint32_t d, const void* s) {
    asm volatile("cp.async.cg.shared.global [%0], [%1], 16;" :: "r"(d), "l"(s));
}
DEV void cp_commit() { asm volatile("cp.async.commit_group;" ::: "memory"); }
DEV void cp_wait2()  { asm volatile("cp.async.wait_group 2;" ::: "memory"); }

DEV void ldsm_x4(uint32_t (&r)[4], uint32_t addr) {
    asm volatile("ldmatrix.sync.aligned.m8n8.x4.shared.b16 {%0,%1,%2,%3}, [%4];"
                 : "=r"(r[0]), "=r"(r[1]), "=r"(r[2]), "=r"(r[3]) : "r"(addr));
}
DEV void mma16816(float (&d)[4], const uint32_t (&a)[4], uint32_t b0, uint32_t b1) {
    asm volatile(
        "mma.sync.aligned.m16n8k16.row.col.f32.bf16.bf16.f32 "
        "{%0,%1,%2,%3}, {%4,%5,%6,%7}, {%8,%9}, {%0,%1,%2,%3};"
        : "+f"(d[0]), "+f"(d[1]), "+f"(d[2]), "+f"(d[3])
        : "r"(a[0]), "r"(a[1]), "r"(a[2]), "r"(a[3]), "r"(b0), "r"(b1));
}

// activation chain + exp (matches reference exactly, in fp32)
DEV float act_exp(float v) {
    v = (v > 0.0f) ? v : 1e-4f * v;            // leaky(0.01) twice
#pragma unroll
    for (int g = 0; g < 2; g++) {              // softsign-GELU twice
        float t = 0.7978845608f * fmaf(0.044715f * v * v, v, v);
        v = 0.5f * v * (1.0f + __fdividef(t, 1.0f + fabsf(t)));
    }
    return __expf(v);
}

// ------------------------------------------------------------- fp32 -> bf16
// Single fused kernel: X then W (no scaling needed for bf16).
DEV uint4 pack8_bf16(float4 a, float4 b) {
    __nv_bfloat162 h0 = __floats2bfloat162_rn(a.x, a.y);
    __nv_bfloat162 h1 = __floats2bfloat162_rn(a.z, a.w);
    __nv_bfloat162 h2 = __floats2bfloat162_rn(b.x, b.y);
    __nv_bfloat162 h3 = __floats2bfloat162_rn(b.z, b.w);
    uint4 o;
    o.x = *reinterpret_cast<uint32_t*>(&h0);
    o.y = *reinterpret_cast<uint32_t*>(&h1);
    o.z = *reinterpret_cast<uint32_t*>(&h2);
    o.w = *reinterpret_cast<uint32_t*>(&h3);
    return o;
}
__global__ void cvt_kernel(const float4* __restrict__ x, const float4* __restrict__ w,
                           int n8x, int n8w) {
    int i = blockIdx.x * blockDim.x + threadIdx.x;
    if (i < n8x) {
        reinterpret_cast<uint4*>(g_Xbf)[i] = pack8_bf16(x[2 * i], x[2 * i + 1]);
    } else if (i - n8x < n8w) {
        int j = i - n8x;
        reinterpret_cast<uint4*>(g_Wbf)[j] = pack8_bf16(w[2 * j], w[2 * j + 1]);
    }
}

// ------------------------------------------------------------- GEMM + epilogue
__global__ void __launch_bounds__(256, 2) gemm_lse_kernel(const float* __restrict__ bias) {
    extern __shared__ char smem[];
    const uint32_t sb = smem_u32(smem);
    const int tid   = threadIdx.x;
    const int lane  = tid & 31;
    const int wid   = tid >> 5;
    const int mwarp = wid >> 2;              // 0..1  (64-row slice)
    const int nwarp = wid & 3;               // 0..3  (32-col slice)
    const int m0 = blockIdx.x * BM;
    const int n0 = blockIdx.y * BN;

    if (tid < BN) reinterpret_cast<float*>(smem + SMEM_BIAS)[tid] = bias[n0 + tid];

    // ---- cp.async slots: 512 x 16B chunks per operand, 2 per thread ----
    uint32_t aDst[2], bDst[2];
    const __nv_bfloat16 *aSrc[2], *bSrc[2];
#pragma unroll
    for (int t = 0; t < 2; t++) {
        int cid = tid + t * 256;
        int r = cid >> 2, c = cid & 3;                  // row, 16B-chunk
        uint32_t off = swz64((uint32_t)(r * 64 + c * 16));
        aDst[t] = sb + SMEM_TILES + off;
        bDst[t] = sb + SMEM_TILES + A_SZ + off;
        aSrc[t] = g_Xbf + (size_t)(m0 + r) * Kdim + c * 8;
        bSrc[t] = g_Wbf + (size_t)(n0 + r) * Kdim + c * 8;
    }

    // ---- ldmatrix per-lane offsets (within stage), all NON-trans ----
    // A x4: lanes 0-15 -> rows 0-15 @ kc0, lanes 16-31 @ kc1; mt*1024 = +16 rows
    // B x4: lanes 0-7 n-oct0/kc0, 8-15 n-oct0/kc1, 16-23 n-oct1/kc0, 24-31 n-oct1/kc1
    //       -> r0,r1 = n-octet(2np) b0,b1 ; r2,r3 = n-octet(2np+1); np*1024 = +16 rows
    uint32_t aOff[2], bOff[2];
#pragma unroll
    for (int kk = 0; kk < 2; kk++) {
        uint32_t ar = (uint32_t)(mwarp * 64 + (lane & 15));
        aOff[kk] = SMEM_TILES +
                   swz64(ar * 64 + (uint32_t)(kk * 32 + (lane >> 4) * 16));
        uint32_t br = (uint32_t)(nwarp * 32 + ((lane >> 4) & 1) * 8 + (lane & 7));
        bOff[kk] = SMEM_TILES + A_SZ +
                   swz64(br * 64 + (uint32_t)(kk * 32 + ((lane >> 3) & 1) * 16));
    }

    float acc[4][4][4];
#pragma unroll
    for (int mt = 0; mt < 4; mt++)
#pragma unroll
        for (int nt = 0; nt < 4; nt++)
#pragma unroll
            for (int j = 0; j < 4; j++) acc[mt][nt][j] = 0.0f;

    // ---- prologue: stages 0..2 ----
#pragma unroll
    for (int s = 0; s < STAGES - 1; s++) {
        uint32_t sB = (uint32_t)(s * STAGE_BYTES);
        int k0 = s * BK;
#pragma unroll
        for (int t = 0; t < 2; t++) {
            cpa16(aDst[t] + sB, aSrc[t] + k0);
            cpa16(bDst[t] + sB, bSrc[t] + k0);
        }
        cp_commit();
    }

    // ---- mainloop (R5 structure: consume, then refill) ----
    for (int i = 0; i < NK; i++) {
        cp_wait2();
        __syncthreads();
        uint32_t sB = (uint32_t)((i & (STAGES - 1)) * STAGE_BYTES);
#pragma unroll
        for (int kk = 0; kk < 2; kk++) {
            uint32_t a[4][4];
#pragma unroll
            for (int mt = 0; mt < 4; mt++)
                ldsm_x4(a[mt], sb + sB + aOff[kk] + mt * 1024);
            uint32_t b[2][4];            // b[np]: r0,r1 = n-oct(2np); r2,r3 = n-oct(2np+1)
#pragma unroll
            for (int np = 0; np < 2; np++)
                ldsm_x4(b[np], sb + sB + bOff[kk] + np * 1024);
#pragma unroll
            for (int mt = 0; mt < 4; mt++)
#pragma unroll
                for (int nt = 0; nt < 4; nt++)
                    mma16816(acc[mt][nt], a[mt],
                             b[nt >> 1][(nt & 1) * 2], b[nt >> 1][(nt & 1) * 2 + 1]);
        }
        int j = i + STAGES - 1;
        if (j < NK) {
            uint32_t fB = (uint32_t)((j & (STAGES - 1)) * STAGE_BYTES);
            int k0 = j * BK;
#pragma unroll
            for (int t = 0; t < 2; t++) {
                cpa16(aDst[t] + fB, aSrc[t] + k0);
                cpa16(bDst[t] + fB, bSrc[t] + k0);
            }
        }
        cp_commit();
    }

    // ---- epilogue: bias + activations + exp + row partial sums ----
    const float* bs = reinterpret_cast<const float*>(smem + SMEM_BIAS);
    const int part = blockIdx.y * 4 + nwarp;
#pragma unroll
    for (int mt = 0; mt < 4; mt++) {
        float sA = 0.0f, sB2 = 0.0f;
#pragma unroll
        for (int nt = 0; nt < 4; nt++) {
            int col = nwarp * 32 + nt * 8 + (lane & 3) * 2;
            float b0 = bs[col], b1 = bs[col + 1];
            sA  += act_exp(acc[mt][nt][0] + b0) + act_exp(acc[mt][nt][1] + b1);
            sB2 += act_exp(acc[mt][nt][2] + b0) + act_exp(acc[mt][nt][3] + b1);
        }
        // combine the 4 lanes (lane&3) that share these two rows
        sA  += __shfl_xor_sync(0xFFFFFFFFu, sA, 1);
        sA  += __shfl_xor_sync(0xFFFFFFFFu, sA, 2);
        sB2 += __shfl_xor_sync(0xFFFFFFFFu, sB2, 1);
        sB2 += __shfl_xor_sync(0xFFFFFFFFu, sB2, 2);
        if ((lane & 3) == 0) {
            int row = m0 + mwarp * 64 + mt * 16 + (lane >> 2);
            g_partial[(size_t)row * NPART + part]       = sA;
            g_partial[(size_t)(row + 8) * NPART + part] = sB2;
        }
    }
}

// ------------------------------------------------------------- final reduce
// Warp per row: coalesced reads, shfl tree (fixed order -> deterministic).
__global__ void lse_kernel(float* __restrict__ out) {
    int warp = (int)((blockIdx.x * blockDim.x + threadIdx.x) >> 5);
    int lane = threadIdx.x & 31;
    if (warp >= Mdim) return;
    const float* p = g_partial + (size_t)warp * NPART;
    float s = (p[lane] + p[lane + 32]) + (p[lane + 64] + p[lane + 96]);
#pragma unroll
    for (int o = 16; o; o >>= 1) s += __shfl_xor_sync(0xFFFFFFFFu, s, o);
    if (lane == 0) out[warp] = logf(s);
}

// ------------------------------------------------------------- launch
extern "C" void kernel_launch(void* const* d_in, const int* in_sizes, int n_in,
                              void* d_out, int out_size) {
    const float* x = (const float*)d_in[0];
    const float* W = (const float*)d_in[1];
    const float* b = (const float*)d_in[2];
    float* out = (float*)d_out;

    cudaFuncSetAttribute(gemm_lse_kernel,
                         cudaFuncAttributeMaxDynamicSharedMemorySize, SMEM_TOTAL);

    int n8x = Mdim * Kdim / 8;
    int n8w = Ndim * Kdim / 8;
    cvt_kernel<<<(n8x + n8w + 255) / 256, 256>>>((const float4*)x, (const float4*)W,
                                                 n8x, n8w);

    gemm_lse_kernel<<<dim3(NTM, NTN), 256, SMEM_TOTAL>>>(b);
    lse_kernel<<<(Mdim * 32 + 255) / 256, 256>>>(out);
}

// round 14
// speedup vs baseline: 1.1602x; 1.0349x over previous
#include <cuda_runtime.h>
#include <cuda_bf16.h>
#include <cstdint>
#include <math.h>

#define DEV __device__ __forceinline__

static constexpr int Mdim = 8192, Kdim = 4096, Ndim = 4096;
static constexpr int BM = 128, BN = 128, BK = 32;       // chunk = K32; macro-iter = 2 chunks
static constexpr int STAGES = 6;                        // 3 pairs
static constexpr int NPAIR = Kdim / (2 * BK);           // 64 macro-iters
static constexpr int NTM = Mdim / BM;                   // 64
static constexpr int NTN = Ndim / BN;                   // 32
static constexpr int A_SZ = BM * 64;                    // 8 KB  (128 rows x 64B)
static constexpr int B_SZ = BN * 64;                    // 8 KB
static constexpr int STAGE_BYTES = A_SZ + B_SZ;         // 16 KB
static constexpr int SMEM_BIAS  = 0;                    // 128 floats
static constexpr int SMEM_TILES = 1024;
static constexpr int SMEM_TOTAL = SMEM_TILES + STAGES * STAGE_BYTES;  // 99328
static constexpr int NPART = NTN * 4;                   // 128 partials per row

// Scratch (__device__ globals: the sanctioned no-alloc path)
__device__ __align__(16) __nv_bfloat16 g_Xbf[(size_t)Mdim * Kdim];
__device__ __align__(16) __nv_bfloat16 g_Wbf[(size_t)Ndim * Kdim];
__device__ float g_partial[(size_t)Mdim * NPART];

// ---------------------------------------------------------------- helpers
DEV uint32_t smem_u32(const void* p) {
    uint32_t a;
    asm("{ .reg .u64 t; cvta.to.shared.u64 t, %1; cvt.u32.u64 %0, t; }"
        : "=r"(a) : "l"(p));
    return a;
}
// SW64-style swizzle for 64B-wide rows: 16B-chunk c' = c ^ ((row>>1)&3).
// Conflict-free for cp.async stores and all ldmatrix 8-address groups.
DEV uint32_t swz64(uint32_t off) { return off ^ ((off >> 3) & 0x30); }

DEV void cpa16(uint32_t d, const void* s) {
    asm volatile("cp.async.cg.shared.global [%0], [%1], 16;" :: "r"(d), "l"(s));
}
DEV void cp_commit() { asm volatile("cp.async.commit_group;" ::: "memory"); }
DEV void cp_wait1()  { asm volatile("cp.async.wait_group 1;" ::: "memory"); }

DEV void ldsm_x4(uint32_t (&r)[4], uint32_t addr) {
    asm volatile("ldmatrix.sync.aligned.m8n8.x4.shared.b16 {%0,%1,%2,%3}, [%4];"
                 : "=r"(r[0]), "=r"(r[1]), "=r"(r[2]), "=r"(r[3]) : "r"(addr));
}
DEV void mma16816(float (&d)[4], const uint32_t (&a)[4], uint32_t b0, uint32_t b1) {
    asm volatile(
        "mma.sync.aligned.m16n8k16.row.col.f32.bf16.bf16.f32 "
        "{%0,%1,%2,%3}, {%4,%5,%6,%7}, {%8,%9}, {%0,%1,%2,%3};"
        : "+f"(d[0]), "+f"(d[1]), "+f"(d[2]), "+f"(d[3])
        : "r"(a[0]), "r"(a[1]), "r"(a[2]), "r"(a[3]), "r"(b0), "r"(b1));
}

// activation chain + exp (matches reference exactly, in fp32)
DEV float act_exp(float v) {
    v = (v > 0.0f) ? v : 1e-4f * v;            // leaky(0.01) twice
#pragma unroll
    for (int g = 0; g < 2; g++) {              // softsign-GELU twice
        float t = 0.7978845608f * fmaf(0.044715f * v * v, v, v);
        v = 0.5f * v * (1.0f + __fdividef(t, 1.0f + fabsf(t)));
    }
    return __expf(v);
}

// ------------------------------------------------------------- fp32 -> bf16
DEV uint4 pack8_bf16(float4 a, float4 b) {
    __nv_bfloat162 h0 = __floats2bfloat162_rn(a.x, a.y);
    __nv_bfloat162 h1 = __floats2bfloat162_rn(a.z, a.w);
    __nv_bfloat162 h2 = __floats2bfloat162_rn(b.x, b.y);
    __nv_bfloat162 h3 = __floats2bfloat162_rn(b.z, b.w);
    uint4 o;
    o.x = *reinterpret_cast<uint32_t*>(&h0);
    o.y = *reinterpret_cast<uint32_t*>(&h1);
    o.z = *reinterpret_cast<uint32_t*>(&h2);
    o.w = *reinterpret_cast<uint32_t*>(&h3);
    return o;
}
__global__ void cvt_kernel(const float4* __restrict__ x, const float4* __restrict__ w,
                           int n8x, int n8w) {
    int i = blockIdx.x * blockDim.x + threadIdx.x;
    if (i < n8x) {
        reinterpret_cast<uint4*>(g_Xbf)[i] = pack8_bf16(x[2 * i], x[2 * i + 1]);
    } else if (i - n8x < n8w) {
        int j = i - n8x;
        reinterpret_cast<uint4*>(g_Wbf)[j] = pack8_bf16(w[2 * j], w[2 * j + 1]);
    }
}

// ------------------------------------------------------------- GEMM + epilogue
__global__ void __launch_bounds__(256, 2) gemm_lse_kernel(const float* __restrict__ bias) {
    extern __shared__ char smem[];
    const uint32_t sb = smem_u32(smem);
    const int tid   = threadIdx.x;
    const int lane  = tid & 31;
    const int wid   = tid >> 5;
    const int mwarp = wid >> 2;              // 0..1  (64-row slice)
    const int nwarp = wid & 3;               // 0..3  (32-col slice)
    const int m0 = blockIdx.x * BM;
    const int n0 = blockIdx.y * BN;

    if (tid < BN) reinterpret_cast<float*>(smem + SMEM_BIAS)[tid] = bias[n0 + tid];

    // ---- cp.async slots: 512 x 16B chunks per operand per K32-chunk ----
    uint32_t aDst[2], bDst[2];
    const __nv_bfloat16 *aSrc[2], *bSrc[2];
#pragma unroll
    for (int t = 0; t < 2; t++) {
        int cid = tid + t * 256;
        int r = cid >> 2, c = cid & 3;                  // row, 16B-chunk
        uint32_t off = swz64((uint32_t)(r * 64 + c * 16));
        aDst[t] = sb + SMEM_TILES + off;
        bDst[t] = sb + SMEM_TILES + A_SZ + off;
        aSrc[t] = g_Xbf + (size_t)(m0 + r) * Kdim + c * 8;
        bSrc[t] = g_Wbf + (size_t)(n0 + r) * Kdim + c * 8;
    }

    // ---- ldmatrix per-lane offsets (within one 16KB stage), all NON-trans ----
    // A x4: lanes 0-15 -> rows 0-15 @ kc0, lanes 16-31 @ kc1; mt*1024 = +16 rows
    // B x4: r0,r1 = n-octet(2np) b0,b1 ; r2,r3 = n-octet(2np+1); np*1024 = +16 rows
    uint32_t aOff[2], bOff[2];
#pragma unroll
    for (int kk = 0; kk < 2; kk++) {
        uint32_t ar = (uint32_t)(mwarp * 64 + (lane & 15));
        aOff[kk] = SMEM_TILES +
                   swz64(ar * 64 + (uint32_t)(kk * 32 + (lane >> 4) * 16));
        uint32_t br = (uint32_t)(nwarp * 32 + ((lane >> 4) & 1) * 8 + (lane & 7));
        bOff[kk] = SMEM_TILES + A_SZ +
                   swz64(br * 64 + (uint32_t)(kk * 32 + ((lane >> 3) & 1) * 16));
    }

    float acc[4][4][4];
#pragma unroll
    for (int mt = 0; mt < 4; mt++)
#pragma unroll
        for (int nt = 0; nt < 4; nt++)
#pragma unroll
            for (int j = 0; j < 4; j++) acc[mt][nt][j] = 0.0f;

    // ---- prologue: 3 pairs (chunks 0..5), one commit per pair ----
#pragma unroll
    for (int p = 0; p < 3; p++) {
#pragma unroll
        for (int s = 0; s < 2; s++) {
            uint32_t sB = (uint32_t)((p * 2 + s) * STAGE_BYTES);
            int k0 = (p * 2 + s) * BK;
#pragma unroll
            for (int t = 0; t < 2; t++) {
                cpa16(aDst[t] + sB, aSrc[t] + k0);
                cpa16(bDst[t] + sB, bSrc[t] + k0);
            }
        }
        cp_commit();
    }

    // ---- mainloop: one sync per K=64 pair (64 iters) ----
    // Group math: at iter i start, committed = 3+i; wait_group 1 => groups
    // #1..#(i+2) complete. Pair i lives in group #(i+1) (prologue, i<=2) or
    // #(i+2) (refilled at iter i-2) -> resident. Distance-2 pipeline needs
    // wait<=1, NOT 2.
    for (int i = 0; i < NPAIR; i++) {
        cp_wait1();
        __syncthreads();     // all warps done reading pair (i-1)%3
        uint32_t pB = (uint32_t)((i % 3) * 2 * STAGE_BYTES);
#pragma unroll
        for (int kq = 0; kq < 4; kq++) {     // 4 x K16 across the two stages
            uint32_t sB = pB + (uint32_t)((kq >> 1) * STAGE_BYTES);
            int kk = kq & 1;
            uint32_t a[4][4];
#pragma unroll
            for (int mt = 0; mt < 4; mt++)
                ldsm_x4(a[mt], sb + sB + aOff[kk] + mt * 1024);
            uint32_t b[2][4];            // b[np]: r0,r1 = n-oct(2np); r2,r3 = n-oct(2np+1)
#pragma unroll
            for (int np = 0; np < 2; np++)
                ldsm_x4(b[np], sb + sB + bOff[kk] + np * 1024);
#pragma unroll
            for (int mt = 0; mt < 4; mt++)
#pragma unroll
                for (int nt = 0; nt < 4; nt++)
                    mma16816(acc[mt][nt], a[mt],
                             b[nt >> 1][(nt & 1) * 2], b[nt >> 1][(nt & 1) * 2 + 1]);
        }
        // refill pair (i+2)%3 == (i-1)%3 (consumed last iter; sync-protected).
        // i==0 skipped: stage still holds live prologue pair 2.
        int j = i + 2;
        if (i >= 1 && j < NPAIR) {
            uint32_t fB = (uint32_t)((j % 3) * 2 * STAGE_BYTES);
#pragma unroll
            for (int s = 0; s < 2; s++) {
                int k0 = (2 * j + s) * BK;
                uint32_t dB = fB + (uint32_t)(s * STAGE_BYTES);
#pragma unroll
                for (int t = 0; t < 2; t++) {
                    cpa16(aDst[t] + dB, aSrc[t] + k0);
                    cpa16(bDst[t] + dB, bSrc[t] + k0);
                }
            }
        }
        cp_commit();         // always commit (empty group keeps the count)
    }

    // ---- epilogue: bias + activations + exp + row partial sums ----
    const float* bs = reinterpret_cast<const float*>(smem + SMEM_BIAS);
    const int part = blockIdx.y * 4 + nwarp;
#pragma unroll
    for (int mt = 0; mt < 4; mt++) {
        float sA = 0.0f, sB2 = 0.0f;
#pragma unroll
        for (int nt = 0; nt < 4; nt++) {
            int col = nwarp * 32 + nt * 8 + (lane & 3) * 2;
            float b0 = bs[col], b1 = bs[col + 1];
            sA  += act_exp(acc[mt][nt][0] + b0) + act_exp(acc[mt][nt][1] + b1);
            sB2 += act_exp(acc[mt][nt][2] + b0) + act_exp(acc[mt][nt][3] + b1);
        }
        // combine the 4 lanes (lane&3) that share these two rows
        sA  += __shfl_xor_sync(0xFFFFFFFFu, sA, 1);
        sA  += __shfl_xor_sync(0xFFFFFFFFu, sA, 2);
        sB2 += __shfl_xor_sync(0xFFFFFFFFu, sB2, 1);
        sB2 += __shfl_xor_sync(0xFFFFFFFFu, sB2, 2);
        if ((lane & 3) == 0) {
            int row = m0 + mwarp * 64 + mt * 16 + (lane >> 2);
            g_partial[(size_t)row * NPART + part]       = sA;
            g_partial[(size_t)(row + 8) * NPART + part] = sB2;
        }
    }
}

// ------------------------------------------------------------- final reduce
// Warp per row: coalesced reads, shfl tree (fixed order -> deterministic).
__global__ void lse_kernel(float* __restrict__ out) {
    int warp = (int)((blockIdx.x * blockDim.x + threadIdx.x) >> 5);
    int lane = threadIdx.x & 31;
    if (warp >= Mdim) return;
    const float* p = g_partial + (size_t)warp * NPART;
    float s = (p[lane] + p[lane + 32]) + (p[lane + 64] + p[lane + 96]);
#pragma unroll
    for (int o = 16; o; o >>= 1) s += __shfl_xor_sync(0xFFFFFFFFu, s, o);
    if (lane == 0) out[warp] = logf(s);
}

// ------------------------------------------------------------- launch
extern "C" void kernel_launch(void* const* d_in, const int* in_sizes, int n_in,
                              void* d_out, int out_size) {
    const float* x = (const float*)d_in[0];
    const float* W = (const float*)d_in[1];
    const float* b = (const float*)d_in[2];
    float* out = (float*)d_out;

    cudaFuncSetAttribute(gemm_lse_kernel,
                         cudaFuncAttributeMaxDynamicSharedMemorySize, SMEM_TOTAL);

    int n8x = Mdim * Kdim / 8;
    int n8w = Ndim * Kdim / 8;
    cvt_kernel<<<(n8x + n8w + 255) / 256, 256>>>((const float4*)x, (const float4*)W,
                                                 n8x, n8w);

    gemm_lse_kernel<<<dim3(NTM, NTN), 256, SMEM_TOTAL>>>(b);
    lse_kernel<<<(Mdim * 32 + 255) / 256, 256>>>(out);
}